// round 16
// baseline (speedup 1.0000x reference)
#include <cuda_runtime.h>
#include <cuda_fp16.h>

// Problem constants: N=1e6 nodes, E=8e6 edges, H=10, ZF=16, OUT=10
#define NN 1000000
#define EE 8000000
#define HD 10
#define HU 8       // h row stride in uint32 units (32B; 20B payload = 1 sector)
#define ZFD 16
#define SLOTS 16   // fixed slots/node (64B line); P(deg>16|Poisson(8)) ~ 0.37% -> overflow list
#define OVMAX 16384

// ---- device scratch ----
__device__ int      g_deg[NN];
__device__ int      g_slot[(size_t)NN * SLOTS];   // 64MB
__device__ int      g_ovf[2 * OVMAX];             // (dst,src) pairs
__device__ int      g_ovcount;
__device__ unsigned g_h0[(size_t)NN * HU];        // fp16x2-packed rows
__device__ unsigned g_h1[(size_t)NN * HU];

// ---------------- encoder (+ deg/ovcount zero): h0 = fp16(z@We^T + be) --------
__global__ void k_enc(const float* __restrict__ z, const float* __restrict__ We,
                      const float* __restrict__ be, int n) {
    __shared__ float sW[HD * ZFD];
    __shared__ float sb[HD];
    int t = threadIdx.x;
    if (t < HD * ZFD) sW[t] = We[t];
    if (t < HD) sb[t] = be[t];
    __syncthreads();
    int i = blockIdx.x * blockDim.x + t;
    if (i >= n) return;
    g_deg[i] = 0;
    if (i == 0) g_ovcount = 0;
    const float4* zp = (const float4*)(z + (size_t)i * ZFD);
    float4 a = zp[0], b4 = zp[1], c4 = zp[2], d4 = zp[3];
    float zv[16] = {a.x, a.y, a.z, a.w, b4.x, b4.y, b4.z, b4.w,
                    c4.x, c4.y, c4.z, c4.w, d4.x, d4.y, d4.z, d4.w};
    unsigned pk[5];
    #pragma unroll
    for (int j = 0; j < 5; j++) {
        float oa = sb[2 * j], ob = sb[2 * j + 1];
        #pragma unroll
        for (int k = 0; k < 16; k++) {
            oa += sW[(2 * j) * 16 + k] * zv[k];
            ob += sW[(2 * j + 1) * 16 + k] * zv[k];
        }
        half2 hp = __floats2half2_rn(oa, ob);
        pk[j] = *(unsigned*)&hp;
    }
    unsigned* op = g_h0 + (size_t)i * HU;
    *(uint4*)op = make_uint4(pk[0], pk[1], pk[2], pk[3]);
    op[4] = pk[4];
}

// ---------------- one-pass adjacency build: 4 edges/thread (int4) -------------
__global__ void k_build(const int* __restrict__ src, const int* __restrict__ dst, int e) {
    int i = blockIdx.x * blockDim.x + threadIdx.x;
    int ebase = i * 4;
    if (ebase + 3 < e) {
        int4 s4 = *(const int4*)(src + ebase);
        int4 d4 = *(const int4*)(dst + ebase);
        int dd[4] = {d4.x, d4.y, d4.z, d4.w};
        int ss[4] = {s4.x, s4.y, s4.z, s4.w};
        #pragma unroll
        for (int k = 0; k < 4; k++) {
            int pos = atomicAdd(&g_deg[dd[k]], 1);
            if (pos < SLOTS) g_slot[(size_t)dd[k] * SLOTS + pos] = ss[k];
            else {
                int o = atomicAdd(&g_ovcount, 1);
                if (o < OVMAX) { g_ovf[2 * o] = dd[k]; g_ovf[2 * o + 1] = ss[k]; }
            }
        }
    } else {
        for (int k = ebase; k < e; k++) {
            int d = dst[k];
            int pos = atomicAdd(&g_deg[d], 1);
            if (pos < SLOTS) g_slot[(size_t)d * SLOTS + pos] = src[k];
            else {
                int o = atomicAdd(&g_ovcount, 1);
                if (o < OVMAX) { g_ovf[2 * o] = d; g_ovf[2 * o + 1] = src[k]; }
            }
        }
    }
}

// ---------------- conv (R9 gather core on slots): half-warp per node ----------
// MODE 0: add+relu (conv1), MODE 1: add (conv2). dir 0: h0->h1, dir 1: h1->h0
template <int MODE>
__global__ void k_conv(const float* __restrict__ W, const float* __restrict__ b,
                       int n, int dir) {
    __shared__ float sW[HD * HD];
    __shared__ float sb[HD];
    int t = threadIdx.x;
    if (t < HD * HD) sW[t] = W[t];
    if (t < HD) sb[t] = b[t];
    __syncthreads();
    const unsigned* __restrict__ in  = dir ? g_h1 : g_h0;
    unsigned* __restrict__       out = dir ? g_h0 : g_h1;

    int lane = t & 31;
    int base = lane & 16;                 // half-warp base
    unsigned hm = 0xFFFFu << base;        // half-warp mask
    int l = lane & 15;                    // 0..15 within half
    int el = l / 5;                       // edge slot 0..2 (l=15 -> 3, inactive)
    int fp = l - el * 5;                  // feature-pair 0..4
    bool act = l < 15;
    int fr = (l < HD) ? l : 0;

    int node = ((blockIdx.x * blockDim.x + t) >> 4);
    if (node >= n) return;

    int dgfull = __ldg(&g_deg[node]);
    int dg = min(dgfull, SLOTS);

    float ax = 0.f, ay = 0.f;
    if (dg > 0) {
        int cidx = __ldg(&g_slot[(size_t)node * SLOTS + min(l, dg - 1)]);  // 1-line block
        #pragma unroll
        for (int s = 0; s < 6; s++) {
            int e = s * 3 + el;
            bool use = act && (e < dg);
            int srcl = base + (use ? e : 0);
            int c = __shfl_sync(hm, cidx, srcl);
            unsigned u = __ldg(&in[(size_t)c * HU + fp]);
            if (use) {
                float2 v = __half22float2(*(half2*)&u);
                ax += v.x; ay += v.y;
            }
        }
    }
    // rare overflow path (deg > SLOTS): scan global overflow list; no shuffles
    if (dgfull > SLOTS && act) {
        int cnt = min(g_ovcount, OVMAX);
        for (int k = el; k < cnt; k += 3) {   // group g handles entries k%3==g
            int d = __ldg(&g_ovf[2 * k]);
            if (d == node) {
                int sc = __ldg(&g_ovf[2 * k + 1]);
                unsigned u = __ldg(&in[(size_t)sc * HU + fp]);
                float2 v = __half22float2(*(half2*)&u);
                ax += v.x; ay += v.y;
            }
        }
    }
    // fold 3 edge slots -> slot 0 (lanes 0..4); capture before accumulating
    {
        float bx = __shfl_sync(hm, ax, base + fp + 5);
        float cx = __shfl_sync(hm, ax, base + fp + 10);
        float by = __shfl_sync(hm, ay, base + fp + 5);
        float cy = __shfl_sync(hm, ay, base + fp + 10);
        ax += bx + cx;
        ay += by + cy;
    }

    // matvec: lanes l<10 compute output features
    float o = 0.f;
    #pragma unroll
    for (int k = 0; k < HD; k += 2) {
        float skx = __shfl_sync(hm, ax, base + (k >> 1));
        float sky = __shfl_sync(hm, ay, base + (k >> 1));
        o = fmaf(sW[fr * HD + k], skx, o);
        o = fmaf(sW[fr * HD + k + 1], sky, o);
    }
    float deg = (float)dgfull;            // true degree for bias
    o += deg * sb[fr];
    if (MODE == 0) o = fmaxf(o, 0.f);

    // pack: lane j<5 stores features {2j, 2j+1}
    float oa = __shfl_sync(hm, o, base + ((l * 2) & 15));
    float ob = __shfl_sync(hm, o, base + ((l * 2 + 1) & 15));
    if (l < 5) {
        half2 hp = __floats2half2_rn(oa, ob);
        out[(size_t)node * HU + l] = *(unsigned*)&hp;
    }
}

// ---------------- fused conv3(mean)+relu + lin + softmax, picked nodes --------
__global__ void k_pickfused(const int* __restrict__ pick,
                            const float* __restrict__ Wc, const float* __restrict__ bc,
                            const float* __restrict__ Wl, const float* __restrict__ bl,
                            float* __restrict__ out, int p, int dir) {
    __shared__ float sWc[HD * HD];
    __shared__ float sbc[HD];
    __shared__ float sWl[HD * HD];
    __shared__ float sbl[HD];
    int t = threadIdx.x;
    if (t < HD * HD) { sWc[t] = Wc[t]; sWl[t] = Wl[t]; }
    if (t < HD) { sbc[t] = bc[t]; sbl[t] = bl[t]; }
    __syncthreads();
    const unsigned* __restrict__ in = dir ? g_h1 : g_h0;

    int lane = t & 31;
    int base = lane & 16;
    unsigned hm = 0xFFFFu << base;
    int l = lane & 15;
    int el = l / 5;
    int fp = l - el * 5;
    bool act = l < 15;
    int fr = (l < HD) ? l : 0;

    int i = ((blockIdx.x * blockDim.x + t) >> 4);
    if (i >= p) return;
    int node = __ldg(&pick[i]);

    int dgfull = __ldg(&g_deg[node]);
    int dg = min(dgfull, SLOTS);

    float ax = 0.f, ay = 0.f;
    if (dg > 0) {
        int cidx = __ldg(&g_slot[(size_t)node * SLOTS + min(l, dg - 1)]);
        #pragma unroll
        for (int s = 0; s < 6; s++) {
            int e = s * 3 + el;
            bool use = act && (e < dg);
            int srcl = base + (use ? e : 0);
            int c = __shfl_sync(hm, cidx, srcl);
            unsigned u = __ldg(&in[(size_t)c * HU + fp]);
            if (use) {
                float2 v = __half22float2(*(half2*)&u);
                ax += v.x; ay += v.y;
            }
        }
    }
    if (dgfull > SLOTS && act) {
        int cnt = min(g_ovcount, OVMAX);
        for (int k = el; k < cnt; k += 3) {
            int d = __ldg(&g_ovf[2 * k]);
            if (d == node) {
                int sc = __ldg(&g_ovf[2 * k + 1]);
                unsigned u = __ldg(&in[(size_t)sc * HU + fp]);
                float2 v = __half22float2(*(half2*)&u);
                ax += v.x; ay += v.y;
            }
        }
    }
    {
        float bx = __shfl_sync(hm, ax, base + fp + 5);
        float cx = __shfl_sync(hm, ax, base + fp + 10);
        float by = __shfl_sync(hm, ay, base + fp + 5);
        float cy = __shfl_sync(hm, ay, base + fp + 10);
        ax += bx + cx;
        ay += by + cy;
    }

    // conv matvec + mean + relu
    float h = 0.f;
    #pragma unroll
    for (int k = 0; k < HD; k += 2) {
        float skx = __shfl_sync(hm, ax, base + (k >> 1));
        float sky = __shfl_sync(hm, ay, base + (k >> 1));
        h = fmaf(sWc[fr * HD + k], skx, h);
        h = fmaf(sWc[fr * HD + k + 1], sky, h);
    }
    float deg = (float)dgfull;
    h = (h + deg * sbc[fr]) / fmaxf(deg, 1.f);
    h = fmaxf(h, 0.f);
    if (l >= HD) h = 0.f;

    // lin matvec
    float lg = 0.f;
    #pragma unroll
    for (int k = 0; k < HD; k++) {
        float hk = __shfl_sync(hm, h, base + k);
        lg = fmaf(sWl[fr * HD + k], hk, lg);
    }
    lg += sbl[fr];

    // softmax over lanes l<HD within the 16-lane group
    float m2 = (l < HD) ? lg : -1e30f;
    #pragma unroll
    for (int off = 8; off > 0; off >>= 1)
        m2 = fmaxf(m2, __shfl_xor_sync(hm, m2, off));
    float ex = (l < HD) ? __expf(lg - m2) : 0.f;
    float sum = ex;
    #pragma unroll
    for (int off = 8; off > 0; off >>= 1)
        sum += __shfl_xor_sync(hm, sum, off);
    if (l < HD) out[(size_t)i * HD + l] = ex / sum;
}

extern "C" void kernel_launch(void* const* d_in, const int* in_sizes, int n_in,
                              void* d_out, int out_size) {
    const float* z    = (const float*)d_in[1];
    const int*   ei   = (const int*)d_in[3];
    const int*   pick = (const int*)d_in[7];
    const float* We   = (const float*)d_in[8];
    const float* be   = (const float*)d_in[9];
    const float* Wz1  = (const float*)d_in[10];
    const float* bz1  = (const float*)d_in[11];
    const float* Wz2  = (const float*)d_in[12];
    const float* bz2  = (const float*)d_in[13];
    const float* Wxz1 = (const float*)d_in[14];
    const float* bxz1 = (const float*)d_in[15];
    const float* Wl   = (const float*)d_in[16];
    const float* bl   = (const float*)d_in[17];
    float* out = (float*)d_out;

    int n = in_sizes[1] / ZFD;
    int e = in_sizes[3] / 2;
    int p = in_sizes[7];
    if (n > NN) n = NN;
    if (e > EE) e = EE;

    const int* src = ei;
    const int* dst = ei + e;

    // encoder (+ deg/ovcount zero)
    k_enc<<<(n + 255) / 256, 256>>>(z, We, be, n);

    // one-pass adjacency build (hist+scan+scatter collapsed; 8M atomics total)
    k_build<<<((e + 3) / 4 + 255) / 256, 256>>>(src, dst, e);

    // conv1 (add+relu): h0 -> h1 ; conv2 (add): h1 -> h0
    int cgrid = (n * 16 + 255) / 256;   // half-warp per node
    k_conv<0><<<cgrid, 256>>>(Wz1, bz1, n, 0);
    k_conv<1><<<cgrid, 256>>>(Wz2, bz2, n, 1);

    // fused conv3(mean)+relu + lin + softmax on picked nodes (reads h0)
    int pgrid = (p * 16 + 255) / 256;
    k_pickfused<<<pgrid, 256>>>(pick, Wxz1, bxz1, Wl, bl, out, p, 0);
}

// round 17
// speedup vs baseline: 2.1453x; 2.1453x over previous
#include <cuda_runtime.h>
#include <cuda_fp16.h>

// Problem constants: N=1e6 nodes, E=8e6 edges, H=10, ZF=16, OUT=10
#define NN 1000000
#define EE 8000000
#define HD 10
#define HU 8       // h row stride in uint32 units (32B; 20B payload = 1 sector)
#define ZFD 16
#define NCMAX 1024

// ---- device scratch ----
__device__ int      g_deg[NN];
__device__ int      g_rowptr[NN + 1];
__device__ int      g_cursor[NN];
__device__ int      g_col[EE];
__device__ unsigned g_h0[(size_t)NN * HU];   // fp16x2-packed rows
__device__ unsigned g_h1[(size_t)NN * HU];
__device__ int      g_csum[NCMAX];

// ---------------- zero deg ----------------
__global__ void k_zero(int n) {
    int i = blockIdx.x * blockDim.x + threadIdx.x;
    if (i < n) g_deg[i] = 0;
}

// ---------------- fused encoder + histogram ----------------
// thread i: enc node i (i<n)  AND  histogram edges [4i, 4i+4)
__global__ void k_enchist(const float* __restrict__ z, const float* __restrict__ We,
                          const float* __restrict__ be, const int* __restrict__ dst,
                          int n, int e) {
    __shared__ float sW[HD * ZFD];
    __shared__ float sb[HD];
    int t = threadIdx.x;
    if (t < HD * ZFD) sW[t] = We[t];
    if (t < HD) sb[t] = be[t];
    __syncthreads();
    int i = blockIdx.x * blockDim.x + t;

    // histogram: 4 edges per thread (int4 load)
    int ebase = i * 4;
    if (ebase + 3 < e) {
        int4 d4 = *(const int4*)(dst + ebase);
        atomicAdd(&g_deg[d4.x], 1);
        atomicAdd(&g_deg[d4.y], 1);
        atomicAdd(&g_deg[d4.z], 1);
        atomicAdd(&g_deg[d4.w], 1);
    } else {
        for (int k = ebase; k < e; k++) atomicAdd(&g_deg[dst[k]], 1);
    }

    // encoder
    if (i >= n) return;
    const float4* zp = (const float4*)(z + (size_t)i * ZFD);
    float4 a = zp[0], b4 = zp[1], c4 = zp[2], d4 = zp[3];
    float zv[16] = {a.x, a.y, a.z, a.w, b4.x, b4.y, b4.z, b4.w,
                    c4.x, c4.y, c4.z, c4.w, d4.x, d4.y, d4.z, d4.w};
    unsigned pk[5];
    #pragma unroll
    for (int j = 0; j < 5; j++) {
        float oa = sb[2 * j], ob = sb[2 * j + 1];
        #pragma unroll
        for (int k = 0; k < 16; k++) {
            oa += sW[(2 * j) * 16 + k] * zv[k];
            ob += sW[(2 * j + 1) * 16 + k] * zv[k];
        }
        half2 hp = __floats2half2_rn(oa, ob);
        pk[j] = *(unsigned*)&hp;
    }
    unsigned* op = g_h0 + (size_t)i * HU;
    *(uint4*)op = make_uint4(pk[0], pk[1], pk[2], pk[3]);
    op[4] = pk[4];
}

// ---------------- scans ----------------
__global__ void k_scan1(int n) {
    int t = threadIdx.x;
    int i = blockIdx.x * 1024 + t;
    int v = (i < n) ? g_deg[i] : 0;
    #pragma unroll
    for (int o = 16; o > 0; o >>= 1) v += __shfl_down_sync(0xffffffffu, v, o);
    __shared__ int sm[32];
    if ((t & 31) == 0) sm[t >> 5] = v;
    __syncthreads();
    if (t < 32) {
        int x = sm[t];
        #pragma unroll
        for (int o = 16; o > 0; o >>= 1) x += __shfl_down_sync(0xffffffffu, x, o);
        if (t == 0) g_csum[blockIdx.x] = x;
    }
}

__global__ void k_scan2(int nc, int n) {
    int t = threadIdx.x;
    int v = (t < nc) ? g_csum[t] : 0;
    __shared__ int sm[1024];
    sm[t] = v;
    __syncthreads();
    for (int o = 1; o < 1024; o <<= 1) {
        int x = (t >= o) ? sm[t - o] : 0;
        __syncthreads();
        sm[t] += x;
        __syncthreads();
    }
    if (t < nc) g_csum[t] = sm[t] - v;
    if (t == 1023) g_rowptr[n] = sm[1023];
}

__global__ void k_scan3(int n) {
    int t = threadIdx.x;
    int i = blockIdx.x * 1024 + t;
    int v = (i < n) ? g_deg[i] : 0;
    __shared__ int sm[1024];
    sm[t] = v;
    __syncthreads();
    for (int o = 1; o < 1024; o <<= 1) {
        int x = (t >= o) ? sm[t - o] : 0;
        __syncthreads();
        sm[t] += x;
        __syncthreads();
    }
    if (i < n) {
        int r = sm[t] - v + g_csum[blockIdx.x];
        g_rowptr[i] = r;
        g_cursor[i] = r;
    }
}

// ---------------- scatter: 2 edges per thread (int2 loads) ----------------
__global__ void k_scatter(const int* __restrict__ src, const int* __restrict__ dst, int e) {
    int i = blockIdx.x * blockDim.x + threadIdx.x;
    int ebase = i * 2;
    if (ebase + 1 < e) {
        int2 s2 = *(const int2*)(src + ebase);
        int2 d2 = *(const int2*)(dst + ebase);
        int p0 = atomicAdd(&g_cursor[d2.x], 1);
        g_col[p0] = s2.x;
        int p1 = atomicAdd(&g_cursor[d2.y], 1);
        g_col[p1] = s2.y;
    } else if (ebase < e) {
        int d = dst[ebase];
        int p = atomicAdd(&g_cursor[d], 1);
        g_col[p] = src[ebase];
    }
}

// ---------------- conv (R9 core): half-warp per node; upfront col block +
// 6 unconditional gather steps (3 edges x 5 half2-lanes), predicated accumulate.
// MODE 0: add+relu (conv1), MODE 1: add (conv2). dir 0: h0->h1, dir 1: h1->h0
template <int MODE>
__global__ void k_conv(const float* __restrict__ W, const float* __restrict__ b,
                       int n, int dir) {
    __shared__ float sW[HD * HD];
    __shared__ float sb[HD];
    int t = threadIdx.x;
    if (t < HD * HD) sW[t] = W[t];
    if (t < HD) sb[t] = b[t];
    __syncthreads();
    const unsigned* __restrict__ in  = dir ? g_h1 : g_h0;
    unsigned* __restrict__       out = dir ? g_h0 : g_h1;

    int lane = t & 31;
    int base = lane & 16;                 // half-warp base
    unsigned hm = 0xFFFFu << base;        // half-warp mask (legal under divergence)
    int l = lane & 15;                    // 0..15 within half
    int el = l / 5;                       // edge slot 0..2 (l=15 -> 3, inactive)
    int fp = l - el * 5;                  // feature-pair 0..4
    bool act = l < 15;
    int fr = (l < HD) ? l : 0;            // clamped output-feature row

    int node = ((blockIdx.x * blockDim.x + t) >> 4);
    if (node >= n) return;

    int beg = __ldg(&g_rowptr[node]);
    int end = __ldg(&g_rowptr[node + 1]);

    float ax = 0.f, ay = 0.f;
    for (int blk = beg; blk < end; blk += 16) {
        int rem = end - blk;                              // > 0
        int m = min(rem, 16);
        int cidx = __ldg(&g_col[blk + min(l, rem - 1)]);  // one coalesced block load
        #pragma unroll
        for (int s = 0; s < 6; s++) {
            int e = s * 3 + el;
            bool use = act && (e < m);
            int srcl = base + (use ? e : 0);
            int c = __shfl_sync(hm, cidx, srcl);          // index from register
            unsigned u = __ldg(&in[(size_t)c * HU + fp]);
            if (use) {
                float2 v = __half22float2(*(half2*)&u);
                ax += v.x; ay += v.y;
            }
        }
    }
    // fold 3 edge slots -> slot 0 (lanes 0..4); capture before accumulating
    {
        float bx = __shfl_sync(hm, ax, base + fp + 5);
        float cx = __shfl_sync(hm, ax, base + fp + 10);
        float by = __shfl_sync(hm, ay, base + fp + 5);
        float cy = __shfl_sync(hm, ay, base + fp + 10);
        ax += bx + cx;
        ay += by + cy;
    }
    // lanes l<5 hold S[2fp], S[2fp+1]

    // matvec: lanes l<10 compute output features
    float o = 0.f;
    #pragma unroll
    for (int k = 0; k < HD; k += 2) {
        float skx = __shfl_sync(hm, ax, base + (k >> 1));
        float sky = __shfl_sync(hm, ay, base + (k >> 1));
        o = fmaf(sW[fr * HD + k], skx, o);
        o = fmaf(sW[fr * HD + k + 1], sky, o);
    }
    float deg = (float)(end - beg);
    o += deg * sb[fr];
    if (MODE == 0) o = fmaxf(o, 0.f);

    // pack: lane j<5 stores features {2j, 2j+1}
    float oa = __shfl_sync(hm, o, base + ((l * 2) & 15));
    float ob = __shfl_sync(hm, o, base + ((l * 2 + 1) & 15));
    if (l < 5) {
        half2 hp = __floats2half2_rn(oa, ob);
        out[(size_t)node * HU + l] = *(unsigned*)&hp;
    }
}

// ---------------- fused conv3(mean)+relu + lin + softmax (picked nodes) -------
__global__ void k_pickfused(const int* __restrict__ pick,
                            const float* __restrict__ Wc, const float* __restrict__ bc,
                            const float* __restrict__ Wl, const float* __restrict__ bl,
                            float* __restrict__ out, int p, int dir) {
    __shared__ float sWc[HD * HD];
    __shared__ float sbc[HD];
    __shared__ float sWl[HD * HD];
    __shared__ float sbl[HD];
    int t = threadIdx.x;
    if (t < HD * HD) { sWc[t] = Wc[t]; sWl[t] = Wl[t]; }
    if (t < HD) { sbc[t] = bc[t]; sbl[t] = bl[t]; }
    __syncthreads();
    const unsigned* __restrict__ in = dir ? g_h1 : g_h0;

    int lane = t & 31;
    int base = lane & 16;
    unsigned hm = 0xFFFFu << base;
    int l = lane & 15;
    int el = l / 5;
    int fp = l - el * 5;
    bool act = l < 15;
    int fr = (l < HD) ? l : 0;

    int i = ((blockIdx.x * blockDim.x + t) >> 4);
    if (i >= p) return;
    int node = __ldg(&pick[i]);

    int beg = __ldg(&g_rowptr[node]);
    int end = __ldg(&g_rowptr[node + 1]);

    float ax = 0.f, ay = 0.f;
    for (int blk = beg; blk < end; blk += 16) {
        int rem = end - blk;
        int m = min(rem, 16);
        int cidx = __ldg(&g_col[blk + min(l, rem - 1)]);
        #pragma unroll
        for (int s = 0; s < 6; s++) {
            int e = s * 3 + el;
            bool use = act && (e < m);
            int srcl = base + (use ? e : 0);
            int c = __shfl_sync(hm, cidx, srcl);
            unsigned u = __ldg(&in[(size_t)c * HU + fp]);
            if (use) {
                float2 v = __half22float2(*(half2*)&u);
                ax += v.x; ay += v.y;
            }
        }
    }
    {
        float bx = __shfl_sync(hm, ax, base + fp + 5);
        float cx = __shfl_sync(hm, ax, base + fp + 10);
        float by = __shfl_sync(hm, ay, base + fp + 5);
        float cy = __shfl_sync(hm, ay, base + fp + 10);
        ax += bx + cx;
        ay += by + cy;
    }

    // conv matvec + mean + relu
    float h = 0.f;
    #pragma unroll
    for (int k = 0; k < HD; k += 2) {
        float skx = __shfl_sync(hm, ax, base + (k >> 1));
        float sky = __shfl_sync(hm, ay, base + (k >> 1));
        h = fmaf(sWc[fr * HD + k], skx, h);
        h = fmaf(sWc[fr * HD + k + 1], sky, h);
    }
    float deg = (float)(end - beg);
    h = (h + deg * sbc[fr]) / fmaxf(deg, 1.f);
    h = fmaxf(h, 0.f);
    if (l >= HD) h = 0.f;

    // lin matvec
    float lg = 0.f;
    #pragma unroll
    for (int k = 0; k < HD; k++) {
        float hk = __shfl_sync(hm, h, base + k);
        lg = fmaf(sWl[fr * HD + k], hk, lg);
    }
    lg += sbl[fr];

    // softmax over lanes l<HD within the 16-lane group
    float m2 = (l < HD) ? lg : -1e30f;
    #pragma unroll
    for (int off = 8; off > 0; off >>= 1)
        m2 = fmaxf(m2, __shfl_xor_sync(hm, m2, off));
    float ex = (l < HD) ? __expf(lg - m2) : 0.f;
    float sum = ex;
    #pragma unroll
    for (int off = 8; off > 0; off >>= 1)
        sum += __shfl_xor_sync(hm, sum, off);
    if (l < HD) out[(size_t)i * HD + l] = ex / sum;
}

extern "C" void kernel_launch(void* const* d_in, const int* in_sizes, int n_in,
                              void* d_out, int out_size) {
    const float* z    = (const float*)d_in[1];
    const int*   ei   = (const int*)d_in[3];
    const int*   pick = (const int*)d_in[7];
    const float* We   = (const float*)d_in[8];
    const float* be   = (const float*)d_in[9];
    const float* Wz1  = (const float*)d_in[10];
    const float* bz1  = (const float*)d_in[11];
    const float* Wz2  = (const float*)d_in[12];
    const float* bz2  = (const float*)d_in[13];
    const float* Wxz1 = (const float*)d_in[14];
    const float* bxz1 = (const float*)d_in[15];
    const float* Wl   = (const float*)d_in[16];
    const float* bl   = (const float*)d_in[17];
    float* out = (float*)d_out;

    int n = in_sizes[1] / ZFD;
    int e = in_sizes[3] / 2;
    int p = in_sizes[7];
    if (n > NN) n = NN;
    if (e > EE) e = EE;

    const int* src = ei;
    const int* dst = ei + e;

    // zero deg, then fused encoder + histogram
    k_zero<<<(n + 255) / 256, 256>>>(n);
    int tot = n > (e + 3) / 4 ? n : (e + 3) / 4;
    k_enchist<<<(tot + 255) / 256, 256>>>(z, We, be, dst, n, e);

    // scans -> rowptr/cursor
    int nc = (n + 1023) / 1024;
    k_scan1<<<nc, 1024>>>(n);
    k_scan2<<<1, 1024>>>(nc, n);
    k_scan3<<<nc, 1024>>>(n);

    // scatter (2 edges/thread)
    k_scatter<<<((e + 1) / 2 + 255) / 256, 256>>>(src, dst, e);

    // conv1 (add+relu): h0 -> h1 ; conv2 (add): h1 -> h0
    int cgrid = (n * 16 + 255) / 256;   // half-warp per node
    k_conv<0><<<cgrid, 256>>>(Wz1, bz1, n, 0);
    k_conv<1><<<cgrid, 256>>>(Wz2, bz2, n, 1);

    // fused conv3(mean)+relu + lin + softmax on picked nodes (reads h0)
    int pgrid = (p * 16 + 255) / 256;
    k_pickfused<<<pgrid, 256>>>(pick, Wxz1, bxz1, Wl, bl, out, p, 0);
}